// round 1
// baseline (speedup 1.0000x reference)
#include <cuda_runtime.h>
#include <math.h>

#define NQ 512
#define NC 65536
#define DIN 768

// Scratch (static device globals — no allocation in kernel_launch).
// Corpus features, SoA: rows 0..31 = e (unit), 32..47 = h (poincare), 48..63 = s (unit), 64 = yn=||h||^2
__device__ float g_cfeatT[65 * NC];
// Query features, SoA: rows 0..63 as above, 64 = xn, 65 = beta = 1-xn, 66..68 = w0,w1,w2
__device__ float g_qfeatT[69 * NQ];
// Hidden relu layer for weight MLP
__device__ float g_qy[NQ * 32];

// ---------------------------------------------------------------------------
// Projection kernel: 64 rows x 64 dims tile, K-chunked GEMM + normalize epilogue
// ---------------------------------------------------------------------------
__global__ __launch_bounds__(256) void proj64_kernel(
    const float* __restrict__ X,
    const float* __restrict__ We, const float* __restrict__ be,
    const float* __restrict__ Wh, const float* __restrict__ bh,
    const float* __restrict__ Ws, const float* __restrict__ bs,
    const float* __restrict__ scale_p,
    float* __restrict__ featT, int fstride, int is_query)
{
    __shared__ __align__(16) float xs[16][68];
    __shared__ __align__(16) float ws[16][68];
    __shared__ __align__(16) float psm[64][68];

    const int tid = threadIdx.x;
    const int r0 = (tid >> 4) * 4;   // row offset within 64-row tile
    const int d0 = (tid & 15) * 4;   // dim offset within 64 dims
    const int row0 = blockIdx.x * 64;

    const int lr = tid >> 2;         // 0..63 : row (for X) / dim (for W)
    const int lk = (tid & 3) * 4;    // k sub-offset 0,4,8,12

    const float* Wrow;
    if (lr < 32)      Wrow = We + lr * DIN;
    else if (lr < 48) Wrow = Wh + (lr - 32) * DIN;
    else              Wrow = Ws + (lr - 48) * DIN;

    float acc[4][4] = {};

    for (int k0 = 0; k0 < DIN; k0 += 16) {
        float4 xv = *(const float4*)(X + (size_t)(row0 + lr) * DIN + k0 + lk);
        float4 wv = *(const float4*)(Wrow + k0 + lk);
        __syncthreads();
        xs[lk + 0][lr] = xv.x; xs[lk + 1][lr] = xv.y;
        xs[lk + 2][lr] = xv.z; xs[lk + 3][lr] = xv.w;
        ws[lk + 0][lr] = wv.x; ws[lk + 1][lr] = wv.y;
        ws[lk + 2][lr] = wv.z; ws[lk + 3][lr] = wv.w;
        __syncthreads();
#pragma unroll
        for (int kk = 0; kk < 16; kk++) {
            float4 a4 = *(const float4*)&xs[kk][r0];
            float4 b4 = *(const float4*)&ws[kk][d0];
            float av[4] = {a4.x, a4.y, a4.z, a4.w};
            float bv[4] = {b4.x, b4.y, b4.z, b4.w};
#pragma unroll
            for (int i = 0; i < 4; i++)
#pragma unroll
                for (int j = 0; j < 4; j++)
                    acc[i][j] = fmaf(av[i], bv[j], acc[i][j]);
        }
    }
    __syncthreads();
#pragma unroll
    for (int i = 0; i < 4; i++)
#pragma unroll
        for (int j = 0; j < 4; j++) {
            int d = d0 + j;
            float bias = (d < 32) ? be[d] : (d < 48) ? bh[d - 32] : bs[d - 48];
            psm[r0 + i][d] = acc[i][j] + bias;
        }
    __syncthreads();

    if (tid < 64) {
        const int r = tid;
        const float sc = *scale_p;
        // e: normalize
        float s2 = 0.f;
#pragma unroll
        for (int k = 0; k < 32; k++) { float v = psm[r][k]; s2 = fmaf(v, v, s2); }
        float inv = 1.0f / sqrtf(s2);
#pragma unroll
        for (int k = 0; k < 32; k++) psm[r][k] *= inv;
        // h: expmap0((.) * scale)
        float h2 = 0.f;
#pragma unroll
        for (int k = 32; k < 48; k++) { float v = psm[r][k] * sc; psm[r][k] = v; h2 = fmaf(v, v, h2); }
        float n  = fmaxf(sqrtf(h2), 1e-15f);
        float th = tanhf(n);
        float fac = th / n;
#pragma unroll
        for (int k = 32; k < 48; k++) psm[r][k] *= fac;
        psm[r][64] = th * th;                    // yn (corpus) / xn (query)
        if (is_query) psm[r][65] = 1.0f - th * th;  // beta
        // s: normalize
        float s3 = 0.f;
#pragma unroll
        for (int k = 48; k < 64; k++) { float v = psm[r][k]; s3 = fmaf(v, v, s3); }
        float inv3 = 1.0f / sqrtf(s3);
#pragma unroll
        for (int k = 48; k < 64; k++) psm[r][k] *= inv3;
    }
    __syncthreads();

    const int nf = is_query ? 66 : 65;
    for (int i = tid; i < nf * 64; i += 256) {
        int k = i >> 6, r = i & 63;
        featT[(size_t)k * fstride + row0 + r] = psm[r][k];
    }
}

// ---------------------------------------------------------------------------
// Weight-MLP layer 1: relu(x_q @ W1.T + b1) -> g_qy [512][32]
// ---------------------------------------------------------------------------
__global__ __launch_bounds__(256) void mlp32_kernel(
    const float* __restrict__ X, const float* __restrict__ W1,
    const float* __restrict__ b1, float* __restrict__ Y)
{
    __shared__ __align__(16) float xs[16][68];
    __shared__ __align__(16) float ws[16][36];
    const int tid = threadIdx.x;
    const int r0 = (tid >> 3) * 2;   // 0..62 even
    const int d0 = (tid & 7) * 4;    // 0..28
    const int row0 = blockIdx.x * 64;
    const int lr = tid >> 2;
    const int lk = (tid & 3) * 4;

    float acc[2][4] = {};
    for (int k0 = 0; k0 < DIN; k0 += 16) {
        float4 xv = *(const float4*)(X + (size_t)(row0 + lr) * DIN + k0 + lk);
        float4 wv = make_float4(0.f, 0.f, 0.f, 0.f);
        if (tid < 128) wv = *(const float4*)(W1 + lr * DIN + k0 + lk);
        __syncthreads();
        xs[lk + 0][lr] = xv.x; xs[lk + 1][lr] = xv.y;
        xs[lk + 2][lr] = xv.z; xs[lk + 3][lr] = xv.w;
        if (tid < 128) {
            ws[lk + 0][lr] = wv.x; ws[lk + 1][lr] = wv.y;
            ws[lk + 2][lr] = wv.z; ws[lk + 3][lr] = wv.w;
        }
        __syncthreads();
#pragma unroll
        for (int kk = 0; kk < 16; kk++) {
            float a0 = xs[kk][r0];
            float a1 = xs[kk][r0 + 1];
            float4 b4 = *(const float4*)&ws[kk][d0];
            float bv[4] = {b4.x, b4.y, b4.z, b4.w};
#pragma unroll
            for (int j = 0; j < 4; j++) {
                acc[0][j] = fmaf(a0, bv[j], acc[0][j]);
                acc[1][j] = fmaf(a1, bv[j], acc[1][j]);
            }
        }
    }
#pragma unroll
    for (int i = 0; i < 2; i++)
#pragma unroll
        for (int j = 0; j < 4; j++)
            Y[(size_t)(row0 + r0 + i) * 32 + d0 + j] =
                fmaxf(acc[i][j] + b1[d0 + j], 0.f);
}

// ---------------------------------------------------------------------------
// Weight-MLP layer 2 + softplus -> g_qfeatT rows 66..68
// ---------------------------------------------------------------------------
__global__ void wmlp_kernel(const float* __restrict__ Y,
                            const float* __restrict__ W2,
                            const float* __restrict__ b2,
                            float* __restrict__ qfT)
{
    int q = blockIdx.x * blockDim.x + threadIdx.x;
    if (q >= NQ) return;
    float z0 = b2[0], z1 = b2[1], z2 = b2[2];
#pragma unroll
    for (int k = 0; k < 32; k++) {
        float y = Y[q * 32 + k];
        z0 = fmaf(y, W2[k],      z0);
        z1 = fmaf(y, W2[32 + k], z1);
        z2 = fmaf(y, W2[64 + k], z2);
    }
    float z[3] = {z0, z1, z2};
#pragma unroll
    for (int j = 0; j < 3; j++) {
        float x = z[j];
        // stable softplus, same form as jax.nn.softplus
        float sp = fmaxf(x, 0.f) + log1pf(expf(-fabsf(x)));
        qfT[(size_t)(66 + j) * NQ + q] = sp;
    }
}

// ---------------------------------------------------------------------------
// Pairwise kernel: 64q x 64c tile, 4x4 register tile, 3 fused K-phases
// ---------------------------------------------------------------------------
__global__ __launch_bounds__(256) void pair_kernel(
    const float* __restrict__ qfT, const float* __restrict__ cfT,
    float* __restrict__ out)
{
    __shared__ __align__(16) float qe[32][64], ce[32][64];
    __shared__ __align__(16) float qh[16][64], ch[16][64];
    __shared__ __align__(16) float qsm[16][64], csm[16][64];
    __shared__ float qxn[64], qbeta[64], qw0[64], qw1[64], qw2[64], cyn[64];

    const int tid = threadIdx.x;
    const int q0 = blockIdx.y * 64;
    const int c0 = blockIdx.x * 64;

    for (int i = tid; i < 64 * 64; i += 256) {
        int k = i >> 6, r = i & 63;
        float qv = qfT[(size_t)k * NQ + q0 + r];
        float cv = cfT[(size_t)k * NC + c0 + r];
        if (k < 32)      { qe[k][r] = qv;       ce[k][r] = cv; }
        else if (k < 48) { qh[k - 32][r] = qv;  ch[k - 32][r] = cv; }
        else             { qsm[k - 48][r] = qv; csm[k - 48][r] = cv; }
    }
    if (tid < 64) {
        int r = tid;
        qxn[r]   = qfT[(size_t)64 * NQ + q0 + r];
        qbeta[r] = qfT[(size_t)65 * NQ + q0 + r];
        qw0[r]   = qfT[(size_t)66 * NQ + q0 + r];
        qw1[r]   = qfT[(size_t)67 * NQ + q0 + r];
        qw2[r]   = qfT[(size_t)68 * NQ + q0 + r];
        cyn[r]   = cfT[(size_t)64 * NC + c0 + r];
    }
    __syncthreads();

    const int cq = (tid >> 4) * 4;   // query offset in tile
    const int cc = (tid & 15) * 4;   // corpus offset in tile

    float w0r[4], w1r[4], w2r[4], xnr[4], betar[4], ynr[4];
#pragma unroll
    for (int i = 0; i < 4; i++) {
        w0r[i] = qw0[cq + i]; w1r[i] = qw1[cq + i]; w2r[i] = qw2[cq + i];
        xnr[i] = qxn[cq + i]; betar[i] = qbeta[cq + i];
    }
#pragma unroll
    for (int j = 0; j < 4; j++) ynr[j] = cyn[cc + j];

    float tot[4][4];
    float acc[4][4];

    // ---- phase e: dist_e = 2 - 2*dot ----
#pragma unroll
    for (int i = 0; i < 4; i++)
#pragma unroll
        for (int j = 0; j < 4; j++) acc[i][j] = 0.f;
#pragma unroll
    for (int k = 0; k < 32; k++) {
        float4 a4 = *(const float4*)&qe[k][cq];
        float4 b4 = *(const float4*)&ce[k][cc];
        float av[4] = {a4.x, a4.y, a4.z, a4.w};
        float bv[4] = {b4.x, b4.y, b4.z, b4.w};
#pragma unroll
        for (int i = 0; i < 4; i++)
#pragma unroll
            for (int j = 0; j < 4; j++)
                acc[i][j] = fmaf(av[i], bv[j], acc[i][j]);
    }
#pragma unroll
    for (int i = 0; i < 4; i++)
#pragma unroll
        for (int j = 0; j < 4; j++)
            tot[i][j] = w0r[i] * (2.f - 2.f * acc[i][j]);

    // ---- phase h: hyperbolic dist^2 ----
#pragma unroll
    for (int i = 0; i < 4; i++)
#pragma unroll
        for (int j = 0; j < 4; j++) acc[i][j] = 0.f;
#pragma unroll
    for (int k = 0; k < 16; k++) {
        float4 a4 = *(const float4*)&qh[k][cq];
        float4 b4 = *(const float4*)&ch[k][cc];
        float av[4] = {a4.x, a4.y, a4.z, a4.w};
        float bv[4] = {b4.x, b4.y, b4.z, b4.w};
#pragma unroll
        for (int i = 0; i < 4; i++)
#pragma unroll
            for (int j = 0; j < 4; j++)
                acc[i][j] = fmaf(av[i], bv[j], acc[i][j]);
    }
#pragma unroll
    for (int i = 0; i < 4; i++) {
        float xn = xnr[i], beta = betar[i];
#pragma unroll
        for (int j = 0; j < 4; j++) {
            float dh = acc[i][j];
            float yn = ynr[j];
            float s1 = fmaf(-2.f, dh, 1.f);        // 1 - 2*dot
            float alpha = s1 + yn;
            float num = fmaf(alpha, fmaf(alpha, xn, -2.f * beta * dh),
                             beta * beta * yn);
            num = fmaxf(num, 0.f);
            float den = fmaxf(fmaf(xn, yn, s1), 1e-15f);
            float t = __fdividef(sqrtf(num), den);
            t = fminf(t, 1.f - 1e-7f);
            float L = __logf(__fdividef(1.f + t, 1.f - t));  // = 2*atanh(t)
            tot[i][j] = fmaf(w1r[i], L * L, tot[i][j]);
        }
    }

    // ---- phase s: arccos(dot)^2 ----
#pragma unroll
    for (int i = 0; i < 4; i++)
#pragma unroll
        for (int j = 0; j < 4; j++) acc[i][j] = 0.f;
#pragma unroll
    for (int k = 0; k < 16; k++) {
        float4 a4 = *(const float4*)&qsm[k][cq];
        float4 b4 = *(const float4*)&csm[k][cc];
        float av[4] = {a4.x, a4.y, a4.z, a4.w};
        float bv[4] = {b4.x, b4.y, b4.z, b4.w};
#pragma unroll
        for (int i = 0; i < 4; i++)
#pragma unroll
            for (int j = 0; j < 4; j++)
                acc[i][j] = fmaf(av[i], bv[j], acc[i][j]);
    }
#pragma unroll
    for (int i = 0; i < 4; i++)
#pragma unroll
        for (int j = 0; j < 4; j++) {
            float d = fminf(fmaxf(acc[i][j], -1.f + 1e-7f), 1.f - 1e-7f);
            float a = acosf(d);
            tot[i][j] = fmaf(w2r[i], a * a, tot[i][j]);
        }

    // ---- store -total ----
#pragma unroll
    for (int i = 0; i < 4; i++) {
        float4 o;
        o.x = -tot[i][0]; o.y = -tot[i][1]; o.z = -tot[i][2]; o.w = -tot[i][3];
        *(float4*)(out + (size_t)(q0 + cq + i) * NC + c0 + cc) = o;
    }
}

// ---------------------------------------------------------------------------
extern "C" void kernel_launch(void* const* d_in, const int* in_sizes, int n_in,
                              void* d_out, int out_size)
{
    const float* x_q  = (const float*)d_in[0];
    const float* x_c  = (const float*)d_in[1];
    const float* We   = (const float*)d_in[2];
    const float* be   = (const float*)d_in[3];
    const float* Wh   = (const float*)d_in[4];
    const float* bh   = (const float*)d_in[5];
    const float* Ws   = (const float*)d_in[6];
    const float* bs   = (const float*)d_in[7];
    const float* scl  = (const float*)d_in[8];
    const float* W1   = (const float*)d_in[9];
    const float* b1   = (const float*)d_in[10];
    const float* W2   = (const float*)d_in[11];
    const float* b2   = (const float*)d_in[12];
    float* out = (float*)d_out;

    float *cfT, *qfT, *qy;
    cudaGetSymbolAddress((void**)&cfT, g_cfeatT);
    cudaGetSymbolAddress((void**)&qfT, g_qfeatT);
    cudaGetSymbolAddress((void**)&qy,  g_qy);

    proj64_kernel<<<NC / 64, 256>>>(x_c, We, be, Wh, bh, Ws, bs, scl, cfT, NC, 0);
    proj64_kernel<<<NQ / 64, 256>>>(x_q, We, be, Wh, bh, Ws, bs, scl, qfT, NQ, 1);
    mlp32_kernel<<<NQ / 64, 256>>>(x_q, W1, b1, qy);
    wmlp_kernel<<<2, 256>>>(qy, W2, b2, qfT);
    pair_kernel<<<dim3(NC / 64, NQ / 64), 256>>>(qfT, cfT, out);
}